// round 17
// baseline (speedup 1.0000x reference)
#include <cuda_runtime.h>

#define B 32
#define S 1024
#define W 512
#define D 768
#define NPOS 32
#define NT 384             // = D/2 threads, one float2 column per thread
#define TOTW (B * W)       // 16384 words
#define CPS 5              // CTAs per SM; 1920 thr/SM, reg budget 32
#define NBLK (148 * CPS * 2)  // 1480: two exact resident waves
#define MAXIT 12           // ceil(TOTW / NBLK)

__global__ void __launch_bounds__(NT, CPS) charpool_f2_kernel(
    const float* __restrict__ feats,      // [B, S, D]
    const int* __restrict__ word_lens,    // [B, W]
    const int* __restrict__ seq_len,      // [B]
    const int* __restrict__ pos,          // [B, W]
    const float* __restrict__ pos_table,  // [NPOS, D]
    float* __restrict__ out)              // [B, W, D]
{
    __shared__ int4 s_meta[MAXIT];        // {start, len, p, valid}

    const int bid = blockIdx.x;
    const int t = threadIdx.x;
    const int dh = D / 2;                 // 384 float2 per row
    const float2* __restrict__ ptab = reinterpret_cast<const float2*>(pos_table);

    const int n = (TOTW - 1 - bid) / NBLK + 1;   // words owned by this CTA (<=12)

    // ---- one-time metadata preamble: thread j resolves word j ----
    if (t < n) {
        const int id = bid + t * NBLK;
        const int w  = id & (W - 1);
        const int b  = id >> 9;
        const int start = __ldg(&word_lens[id]);
        const int nxt   = (w + 1 < W) ? __ldg(&word_lens[id + 1]) : 0;
        const int end   = (nxt == 0) ? __ldg(&seq_len[b]) : nxt;
        int len = end - start;
        if (len < 1) len = 1;
        const int valid = (start != 0) || (w == 0);
        s_meta[t] = make_int4(start, len, __ldg(&pos[id]), valid);
    }
    __syncthreads();

    // ---- main loop: no barriers; float2 payload keeps live regs <= 32 ----
    for (int k = 0; k < n; ++k) {
        const int4 md = s_meta[k];                 // start, len, p, valid
        const int id = bid + k * NBLK;

        const float2 pt = ptab[md.z * dh + t];
        float2 r;

        if (md.w) {
            const int len = md.y;
            const float2* fp = reinterpret_cast<const float2*>(
                feats + ((size_t)(id >> 9) * S + (size_t)md.x) * D) + t;

            float2 acc = make_float2(0.f, 0.f);
            const float2 z = make_float2(0.f, 0.f);
            for (int s = 0; s < len; s += 4) {
                // up to 4 independent row loads issued before any consume
                float2 v0 = fp[0 * dh];
                float2 v1 = (s + 1 < len) ? fp[1 * dh] : z;
                float2 v2 = (s + 2 < len) ? fp[2 * dh] : z;
                float2 v3 = (s + 3 < len) ? fp[3 * dh] : z;
                acc.x += (v0.x + v1.x) + (v2.x + v3.x);
                acc.y += (v0.y + v1.y) + (v2.y + v3.y);
                fp += 4 * dh;
            }
            const float inv = 1.0f / (float)len;
            r.x = fmaf(acc.x, inv, pt.x);
            r.y = fmaf(acc.y, inv, pt.y);
        } else {
            r = pt;   // pos=0 table row is zero -> zeros for padding words
        }

        // streaming store: out has zero reuse; don't displace L2-resident feats
        __stcs(reinterpret_cast<float2*>(out + (size_t)id * D) + t, r);
    }
}

extern "C" void kernel_launch(void* const* d_in, const int* in_sizes, int n_in,
                              void* d_out, int out_size)
{
    const float* feats     = (const float*)d_in[0];
    const int*   word_lens = (const int*)d_in[1];
    const int*   seq_len   = (const int*)d_in[2];
    const int*   pos       = (const int*)d_in[3];
    const float* pos_table = (const float*)d_in[4];
    float* out = (float*)d_out;

    charpool_f2_kernel<<<NBLK, NT>>>(feats, word_lens, seq_len, pos, pos_table, out);
}